// round 15
// baseline (speedup 1.0000x reference)
#include <cuda_runtime.h>
#include <math.h>

#define Bsz   1024
#define Nn    32
#define SE    10
#define OOUT  5
#define IIN   6
#define GPB   16     // samples per block
#define TPB   256    // 8 warps = 4 pairs; pair owns 4 samples; warp owns 30 dims

// ---- shared memory layout (float offsets; all 16B-aligned) ----
#define S_WHH 0        // 180 x 68 = 12240  (adj scratch first, head weights last)
#define S_WIH 12240    // 12240
#define S_WF  24480    // 60 x 84 = 5040
#define S_BIH 29520    // 180
#define S_BF  29700    // 60
#define S_HAS 29760    // 16*32 = 512
#define S_ZD  30272    // 16*20 = 320
#define S_H   30592    // 4 pairs x 2 bufs x 4 samples x 64 = 2048
#define S_RHO 32640    // 16*64 = 1024
#define S_CNT 33664    // 32 ints
#define S_LST 33696    // 32*32 ints
#define SMEM_FLOATS 34720   // ~139 KB -> 1 block/SM

// head-weight staging offsets (reuse S_WHH region after scan)
#define HW_WU 0        // 840
#define HW_BU 840      // 7
#define HW_WA 848      // 600
#define HW_WC 1448     // 120
#define HW_BA 1568     // 5
#define HW_BC 1573     // 1

// ---- device scratch ----
// rho layout is B-MAJOR: [b][n][60]
__device__ float g_rho_f[Bsz * Nn * 60];
__device__ float g_rho_b[Bsz * Nn * 60];
__device__ float g_af[Bsz * 60];
__device__ float g_ab[Bsz * 60];
__device__ float g_gi_f[Nn * Bsz * 180];   // gi cache incl. bih: [node][b][row]
__device__ float g_gi_b[Nn * Bsz * 180];
__device__ int   g_done[64];               // pairwise arrival counters (monotonic)

__device__ __forceinline__ void fma2(unsigned long long& a,
                                     unsigned long long b, unsigned long long c) {
    asm("fma.rn.f32x2 %0,%1,%2,%0;" : "+l"(a) : "l"(b), "l"(c));
}
__device__ __forceinline__ float red2(unsigned long long v) {
    float x, y;
    asm("mov.b64 {%0,%1},%2;" : "=f"(x), "=f"(y) : "l"(v));
    return x + y;
}
__device__ __forceinline__ unsigned long long seed2(float x) {
    return (unsigned long long)__float_as_uint(x);   // (x, +0.0f)
}
__device__ __forceinline__ float sigmf_(float x) {
    return __fdividef(1.0f, 1.0f + __expf(-x));
}
__device__ __forceinline__ float tanhsafe_(float x) {
    float a = fabsf(x);
    float e = __expf(-2.0f * a);
    float t = __fdividef(1.0f - e, 1.0f + e);
    return copysignf(t, x);
}
#define PAIRBAR(id) asm volatile("bar.sync %0, %1;" :: "r"(id), "r"(64) : "memory")

// ============================================================
// Fused scan + heads: 128 blocks (64 fwd, 64 bwd), 16 samples each.
// Scan identical to the validated 301us kernel. After the alpha scan,
// fwd/bwd partner blocks handshake (round-based counter, replay-safe)
// and compute the output heads for their shared 16 samples.
// ============================================================
__global__ void __launch_bounds__(TPB) k_scan(
    const unsigned char* __restrict__ adj_raw,
    const float* __restrict__ has, const float* __restrict__ z, const float* __restrict__ dz,
    const float* __restrict__ Wih_f, const float* __restrict__ Whh_f,
    const float* __restrict__ bih_f, const float* __restrict__ bhh_f,
    const float* __restrict__ Wih_b, const float* __restrict__ Whh_b,
    const float* __restrict__ bih_b, const float* __restrict__ bhh_b,
    const float* __restrict__ Wfp, const float* __restrict__ bfp,
    const float* __restrict__ Wbp, const float* __restrict__ bbp,
    const float* __restrict__ Wu, const float* __restrict__ bu,
    const float* __restrict__ Wa, const float* __restrict__ ba,
    const float* __restrict__ Wc, const float* __restrict__ bc,
    float* __restrict__ out)
{
    extern __shared__ __align__(16) float sm[];
    int* smi = (int*)sm;
    const int dir = blockIdx.x >> 6;
    const int pg  = blockIdx.x & 63;
    const int b0  = pg * GPB;
    const float* Wih = dir ? Wih_b : Wih_f;
    const float* Whh = dir ? Whh_b : Whh_f;
    const float* bih = dir ? bih_b : bih_f;
    const float* bhh = dir ? bhh_b : bhh_f;
    const float* Wp  = dir ? Wbp   : Wfp;
    const float* bp  = dir ? bbp   : bfp;
    float* grho = dir ? g_rho_b : g_rho_f;
    float* gic  = dir ? g_gi_b  : g_gi_f;

    const int  tid   = threadIdx.x;
    const int  warp  = tid >> 5;
    const int  lane  = tid & 31;
    const int  pair  = warp >> 1;        // 0..3
    const int  half  = warp & 1;         // 0: dims 0-29, 1: dims 30-59
    const int  sb    = pair * 4;         // pair's sample base
    const int  lpair = half * 32 + lane; // 0..63 within pair
    const int  barid = 1 + pair;
    const bool act   = lane < 30;
    const int  d     = half * 30 + lane; // owned dim (if act)

    // ---- fused prep: decode adj (dtype-ambiguous) + edge lists for this dir
    if (tid < 2) smi[1024 + tid] = 0;
    __syncthreads();
    {
        int f_gt1 = 0, f_off4 = 0;
        for (int t = tid; t < Nn * Nn; t += TPB) {
            unsigned char c = adj_raw[t];
            if (c > 1) f_gt1 = 1;
            if (c == 1 && (t & 3) != 0) f_off4 = 1;
        }
        if (f_gt1)  atomicOr(&smi[1024], 1);
        if (f_off4) atomicOr(&smi[1025], 1);
    }
    __syncthreads();
    {
        const int mode = smi[1024] ? 1 : (smi[1025] ? 0 : 2);
        for (int e = tid; e < Nn * Nn; e += TPB) {
            float v;
            if (mode == 1)      v = ((const float*)adj_raw)[e];
            else if (mode == 2) v = (float)(((const int*)adj_raw)[e]);
            else                v = (float)adj_raw[e];
            sm[e] = v;
        }
    }
    __syncthreads();
    if (tid < Nn) {
        const int i = tid; int c = 0;
        if (dir == 0) {
            for (int j = 0; j < Nn; j++)
                if (sm[j * Nn + i] != 0.0f) smi[S_LST + i * 32 + (c++)] = j;
        } else {
            for (int j = Nn - 1; j >= 0; j--)
                if (sm[i * Nn + j] != 0.0f) smi[S_LST + i * 32 + (c++)] = j;
        }
        smi[S_CNT + i] = c;
    }
    __syncthreads();

    // ---- block-wide weight/bias staging (overwrites adj scratch)
    for (int idx = tid; idx < 10800; idx += TPB) {
        const int r = idx / 60, c = idx - r * 60;
        sm[S_WHH + r * 68 + c] = Whh[idx];
        sm[S_WIH + r * 68 + c] = Wih[idx];
    }
    for (int idx = tid; idx < 4800; idx += TPB)
        sm[S_WF + (idx / 80) * 84 + (idx % 80)] = Wp[idx];
    for (int idx = tid; idx < 180; idx += TPB) sm[S_BIH + idx] = bih[idx];
    for (int idx = tid; idx < 60;  idx += TPB) sm[S_BF + idx]  = bp[idx];
    for (int idx = tid; idx < GPB * Nn; idx += TPB)
        sm[S_HAS + idx] = has[(size_t)(b0 + (idx >> 5)) * Nn + (idx & 31)];
    __syncthreads();

    const float bhh0 = act ? bhh[d]        : 0.0f;
    const float bhh1 = act ? bhh[60 + d]   : 0.0f;
    const float bhh2 = act ? bhh[120 + d]  : 0.0f;
    const float bih0 = act ? sm[S_BIH + d]        : 0.0f;
    const float bih1 = act ? sm[S_BIH + 60 + d]   : 0.0f;
    const float bih2 = act ? sm[S_BIH + 120 + d]  : 0.0f;

    float* sHp = sm + S_H + pair * 512;   // [buf 2][sample 4][64]
    const float* w0p = sm + S_WHH + d * 68;
    const float* w1p = sm + S_WHH + (60 + d) * 68;
    const float* w2p = sm + S_WHH + (120 + d) * 68;

    int rp = 0;
    float h_old[4];
    float gi0[4], gi1[4], gi2[4], gn0[4], gn1[4], gn2[4];
    float a0[4], a1[4], a2[4];

    // ================== node scan ==================
    for (int ii = 0; ii < Nn; ii++) {
        const int i = dir ? (Nn - 1 - ii) : ii;

        for (int idx = lpair; idx < 80; idx += 64) {
            const int m = idx / 20, c = idx % 20;
            const size_t base = ((size_t)(b0 + sb + m) * Nn + i) * SE;
            sm[S_ZD + (sb + m) * 20 + c] = (c < SE) ? z[base + c] : dz[base + c - SE];
        }

        const int  cnt = smi[S_CNT + i];
        const int* lst = smi + S_LST + i * 32;

        #pragma unroll
        for (int m = 0; m < 4; m++) h_old[m] = 0.0f;

        if (cnt == 0) {
            if (act) {
                #pragma unroll
                for (int m = 0; m < 4; m++) sHp[rp * 256 + m * 64 + d] = 0.0f;
            }
            PAIRBAR(barid);
        } else {
            if (act) {
                const float* gb = gic + ((size_t)lst[0] * Bsz + b0 + sb) * 180;
                #pragma unroll
                for (int m = 0; m < 4; m++) {
                    gi0[m] = gb[m * 180 + d];
                    gi1[m] = gb[m * 180 + 60 + d];
                    gi2[m] = gb[m * 180 + 120 + d];
                }
            }
            for (int e = 0; e < cnt; e++) {
                const int j = lst[e];
                if (act) {
                    if (e > 0) {
                        unsigned long long A0[4], A1[4], A2[4];
                        #pragma unroll
                        for (int m = 0; m < 4; m++) { A0[m]=0; A1[m]=0; A2[m]=0; }
                        const float* Hb = sHp + rp * 256;
                        #pragma unroll
                        for (int q = 0; q < 15; q++) {
                            const ulonglong2 w0 = *(const ulonglong2*)(w0p + q * 4);
                            const ulonglong2 w1 = *(const ulonglong2*)(w1p + q * 4);
                            const ulonglong2 w2 = *(const ulonglong2*)(w2p + q * 4);
                            #pragma unroll
                            for (int m = 0; m < 4; m++) {
                                const ulonglong2 h = *(const ulonglong2*)(Hb + m * 64 + q * 4);
                                fma2(A0[m], w0.x, h.x); fma2(A0[m], w0.y, h.y);
                                fma2(A1[m], w1.x, h.x); fma2(A1[m], w1.y, h.y);
                                fma2(A2[m], w2.x, h.x); fma2(A2[m], w2.y, h.y);
                            }
                        }
                        #pragma unroll
                        for (int m = 0; m < 4; m++) {
                            a0[m] = red2(A0[m]); a1[m] = red2(A1[m]); a2[m] = red2(A2[m]);
                        }
                    } else {
                        #pragma unroll
                        for (int m = 0; m < 4; m++) { a0[m]=0; a1[m]=0; a2[m]=0; }
                    }
                    if (e + 1 < cnt) {
                        const float* gb = gic + ((size_t)lst[e + 1] * Bsz + b0 + sb) * 180;
                        #pragma unroll
                        for (int m = 0; m < 4; m++) {
                            gn0[m] = gb[m * 180 + d];
                            gn1[m] = gb[m * 180 + 60 + d];
                            gn2[m] = gb[m * 180 + 120 + d];
                        }
                    }
                    #pragma unroll
                    for (int m = 0; m < 4; m++) {
                        const float mask = sm[S_HAS + (sb + m) * 32 + j];
                        const float r  = sigmf_(a0[m] + gi0[m] + bhh0);
                        const float u  = sigmf_(a1[m] + gi1[m] + bhh1);
                        const float nv = tanhsafe_(gi2[m] + r * (a2[m] + bhh2));
                        const float ho = h_old[m];
                        const float h2 = (1.0f - u) * nv + u * ho;
                        const float hn = ho + mask * (h2 - ho);
                        h_old[m] = hn;
                        sHp[(1 - rp) * 256 + m * 64 + d] = hn;
                    }
                    if (e + 1 < cnt) {
                        #pragma unroll
                        for (int m = 0; m < 4; m++) {
                            gi0[m]=gn0[m]; gi1[m]=gn1[m]; gi2[m]=gn2[m];
                        }
                    }
                }
                PAIRBAR(barid);
                rp ^= 1;
            }
        }

        // ---- projection
        if (act) {
            const ulonglong2* Wr = (const ulonglong2*)(sm + S_WF + d * 84);
            #pragma unroll
            for (int m = 0; m < 4; m++) {
                unsigned long long acc = seed2(sm[S_BF + d]);
                const ulonglong2* Hh = (const ulonglong2*)(sHp + rp * 256 + m * 64);
                #pragma unroll
                for (int q = 0; q < 15; q++) {
                    const ulonglong2 w = Wr[q], h = Hh[q];
                    fma2(acc, w.x, h.x); fma2(acc, w.y, h.y);
                }
                const ulonglong2* Zd = (const ulonglong2*)(sm + S_ZD + (sb + m) * 20);
                #pragma unroll
                for (int q = 0; q < 5; q++) {
                    const ulonglong2 w = Wr[15 + q], x = Zd[q];
                    fma2(acc, w.x, x.x); fma2(acc, w.y, x.y);
                }
                float val = red2(acc);
                if (dir == 0) val = tanhsafe_(val);
                sm[S_RHO + (sb + m) * 64 + d] = val;
                grho[((size_t)(b0 + sb + m) * Nn + i) * 60 + d] = val;   // b-major
            }
        }
        PAIRBAR(barid);

        // ---- gi for node i
        if (act) {
            unsigned long long A0[4], A1[4], A2[4];
            #pragma unroll
            for (int m = 0; m < 4; m++) {
                A0[m] = seed2(bih0); A1[m] = seed2(bih1); A2[m] = seed2(bih2);
            }
            const float* u0p = sm + S_WIH + d * 68;
            const float* u1p = sm + S_WIH + (60 + d) * 68;
            const float* u2p = sm + S_WIH + (120 + d) * 68;
            const float* Rb = sm + S_RHO + sb * 64;
            #pragma unroll
            for (int q = 0; q < 15; q++) {
                const ulonglong2 w0 = *(const ulonglong2*)(u0p + q * 4);
                const ulonglong2 w1 = *(const ulonglong2*)(u1p + q * 4);
                const ulonglong2 w2 = *(const ulonglong2*)(u2p + q * 4);
                #pragma unroll
                for (int m = 0; m < 4; m++) {
                    const ulonglong2 rv = *(const ulonglong2*)(Rb + m * 64 + q * 4);
                    fma2(A0[m], w0.x, rv.x); fma2(A0[m], w0.y, rv.y);
                    fma2(A1[m], w1.x, rv.x); fma2(A1[m], w1.y, rv.y);
                    fma2(A2[m], w2.x, rv.x); fma2(A2[m], w2.y, rv.y);
                }
            }
            #pragma unroll
            for (int m = 0; m < 4; m++) {
                float* gp = gic + ((size_t)i * Bsz + b0 + sb + m) * 180;
                gp[d]       = red2(A0[m]);
                gp[60 + d]  = red2(A1[m]);
                gp[120 + d] = red2(A2[m]);
            }
        }
    }

    // ================== alpha scan ==================
    #pragma unroll
    for (int m = 0; m < 4; m++) h_old[m] = 0.0f;
    const int steps = dir ? IIN : OOUT;
    for (int s = 0; s < steps; s++) {
        const int i = dir ? (IIN - 1 - s) : (Nn - OOUT + s);
        if (act) {
            const float* gb = gic + ((size_t)i * Bsz + b0 + sb) * 180;
            #pragma unroll
            for (int m = 0; m < 4; m++) {
                gi0[m] = gb[m * 180 + d];
                gi1[m] = gb[m * 180 + 60 + d];
                gi2[m] = gb[m * 180 + 120 + d];
            }
            if (s > 0) {
                unsigned long long A0[4], A1[4], A2[4];
                #pragma unroll
                for (int m = 0; m < 4; m++) { A0[m]=0; A1[m]=0; A2[m]=0; }
                const float* Hb = sHp + rp * 256;
                #pragma unroll
                for (int q = 0; q < 15; q++) {
                    const ulonglong2 w0 = *(const ulonglong2*)(w0p + q * 4);
                    const ulonglong2 w1 = *(const ulonglong2*)(w1p + q * 4);
                    const ulonglong2 w2 = *(const ulonglong2*)(w2p + q * 4);
                    #pragma unroll
                    for (int m = 0; m < 4; m++) {
                        const ulonglong2 h = *(const ulonglong2*)(Hb + m * 64 + q * 4);
                        fma2(A0[m], w0.x, h.x); fma2(A0[m], w0.y, h.y);
                        fma2(A1[m], w1.x, h.x); fma2(A1[m], w1.y, h.y);
                        fma2(A2[m], w2.x, h.x); fma2(A2[m], w2.y, h.y);
                    }
                }
                #pragma unroll
                for (int m = 0; m < 4; m++) {
                    a0[m] = red2(A0[m]); a1[m] = red2(A1[m]); a2[m] = red2(A2[m]);
                }
            } else {
                #pragma unroll
                for (int m = 0; m < 4; m++) { a0[m]=0; a1[m]=0; a2[m]=0; }
            }
            #pragma unroll
            for (int m = 0; m < 4; m++) {
                const float mask = sm[S_HAS + (sb + m) * 32 + i];
                const float r  = sigmf_(a0[m] + gi0[m] + bhh0);
                const float u  = sigmf_(a1[m] + gi1[m] + bhh1);
                const float nv = tanhsafe_(gi2[m] + r * (a2[m] + bhh2));
                const float ho = h_old[m];
                const float h2 = (1.0f - u) * nv + u * ho;
                const float hn = ho + mask * (h2 - ho);
                h_old[m] = hn;
                sHp[(1 - rp) * 256 + m * 64 + d] = hn;
            }
        }
        PAIRBAR(barid);
        rp ^= 1;
    }
    if (act) {
        float* ga = dir ? g_ab : g_af;
        #pragma unroll
        for (int m = 0; m < 4; m++)
            ga[(size_t)(b0 + sb + m) * 60 + d] = h_old[m];
    }

    // ================== pairwise handshake + fused heads ==================
    __threadfence();          // release: rho/alpha visible device-wide
    __syncthreads();          // all threads' writes precede the arrive
    if (tid == 0) {
        const int old = atomicAdd(&g_done[pg], 1);
        const int target = (old & ~1) + 2;        // replay-safe round target
        while (*(volatile int*)&g_done[pg] < target) { }
        __threadfence();      // acquire: partner's writes now visible
    }
    __syncthreads();

    // stage head weights (reuse S_WHH smem region)
    for (int idx = tid; idx < 840; idx += TPB) sm[HW_WU + idx] = Wu[idx];
    for (int idx = tid; idx < 600; idx += TPB) sm[HW_WA + idx] = Wa[idx];
    for (int idx = tid; idx < 120; idx += TPB) sm[HW_WC + idx] = Wc[idx];
    if (tid < 7)  sm[HW_BU + tid] = bu[tid];
    if (tid < 5)  sm[HW_BA + tid] = ba[tid];
    if (tid == 0) sm[HW_BC] = bc[0];
    __syncthreads();

    // ---- roles: this block handles 8 samples (fwd: first 8; bwd: last 8)
    {
        const int m8 = tid >> 5;                 // 0..7
        const int n  = tid & 31;
        const int b  = b0 + dir * 8 + m8;

        float acc[7];
        #pragma unroll
        for (int r = 0; r < 7; r++) acc[r] = sm[HW_BU + r];

        const float4* rf = (const float4*)(g_rho_f + ((size_t)b * Nn + n) * 60);
        const float4* rb = (const float4*)(g_rho_b + ((size_t)b * Nn + n) * 60);
        #pragma unroll
        for (int q = 0; q < 15; q++) {
            const float4 f = rf[q];
            #pragma unroll
            for (int r = 0; r < 7; r++) {
                const float4 w = *(const float4*)(sm + HW_WU + r * 120 + q * 4);
                acc[r] += w.x*f.x + w.y*f.y + w.z*f.z + w.w*f.w;
            }
        }
        #pragma unroll
        for (int q = 0; q < 15; q++) {
            const float4 f = rb[q];
            #pragma unroll
            for (int r = 0; r < 7; r++) {
                const float4 w = *(const float4*)(sm + HW_WU + r * 120 + 60 + q * 4);
                acc[r] += w.x*f.x + w.y*f.y + w.z*f.z + w.w*f.w;
            }
        }
        const float msk = sm[S_HAS + (dir * 8 + m8) * 32 + n];
        float l[7], mx = -1e30f;
        #pragma unroll
        for (int r = 0; r < 7; r++) { l[r] = (msk != 0.0f) ? acc[r] : -60.0f; mx = fmaxf(mx, l[r]); }
        float s = 0.0f;
        #pragma unroll
        for (int r = 0; r < 7; r++) { l[r] = __expf(l[r] - mx); s += l[r]; }
        const float inv = __fdividef(1.0f, s);
        float* ro = out + 5120;
        #pragma unroll
        for (int r = 0; r < 7; r++) ro[((size_t)b * 7 + r) * 32 + n] = l[r] * inv;
    }

    // ---- instr + value: bwd block only, 4 lanes per sample (tid < 64)
    if (dir == 1 && tid < 64) {
        const int b    = b0 + (tid >> 2);
        const int lane4 = tid & 3;

        float acc[6];
        #pragma unroll
        for (int a = 0; a < 6; a++) acc[a] = 0.0f;

        const float4* af = (const float4*)(g_af + (size_t)b * 60);
        const float4* ab = (const float4*)(g_ab + (size_t)b * 60);
        for (int q = lane4; q < 30; q += 4) {
            const float4 f = (q < 15) ? af[q] : ab[q - 15];
            #pragma unroll
            for (int a = 0; a < 5; a++) {
                const float4 w = *(const float4*)(sm + HW_WA + a * 120 + q * 4);
                acc[a] += w.x*f.x + w.y*f.y + w.z*f.z + w.w*f.w;
            }
            const float4 wc = *(const float4*)(sm + HW_WC + q * 4);
            acc[5] += wc.x*f.x + wc.y*f.y + wc.z*f.z + wc.w*f.w;
        }
        #pragma unroll
        for (int off = 1; off < 4; off <<= 1) {
            #pragma unroll
            for (int a = 0; a < 6; a++)
                acc[a] += __shfl_xor_sync(0xffffffffu, acc[a], off);
        }
        if (lane4 == 0) {
            float l[5], mx = -1e30f;
            #pragma unroll
            for (int a = 0; a < 5; a++) { l[a] = acc[a] + sm[HW_BA + a]; mx = fmaxf(mx, l[a]); }
            float s = 0.0f;
            #pragma unroll
            for (int a = 0; a < 5; a++) { l[a] = __expf(l[a] - mx); s += l[a]; }
            const float inv = __fdividef(1.0f, s);
            #pragma unroll
            for (int a = 0; a < 5; a++) out[b * 5 + a] = l[a] * inv;
            out[5120 + Bsz * 7 * Nn + b] = acc[5] + sm[HW_BC];   // value @ 234496
        }
    }
}

// ============================================================
extern "C" void kernel_launch(void* const* d_in, const int* in_sizes, int n_in,
                              void* d_out, int out_size)
{
    const float* has   = (const float*)d_in[0];
    const float* z     = (const float*)d_in[1];
    const float* dz    = (const float*)d_in[2];
    const unsigned char* adj = (const unsigned char*)d_in[3];
    const float* Wih_f = (const float*)d_in[4];
    const float* Whh_f = (const float*)d_in[5];
    const float* bih_f = (const float*)d_in[6];
    const float* bhh_f = (const float*)d_in[7];
    const float* Wih_b = (const float*)d_in[8];
    const float* Whh_b = (const float*)d_in[9];
    const float* bih_b = (const float*)d_in[10];
    const float* bhh_b = (const float*)d_in[11];
    const float* Wf    = (const float*)d_in[12];
    const float* bf    = (const float*)d_in[13];
    const float* Wb    = (const float*)d_in[14];
    const float* bb    = (const float*)d_in[15];
    const float* Wa    = (const float*)d_in[16];
    const float* ba    = (const float*)d_in[17];
    const float* Wc    = (const float*)d_in[18];
    const float* bc    = (const float*)d_in[19];
    const float* Wu    = (const float*)d_in[20];
    const float* bu    = (const float*)d_in[21];
    float* out = (float*)d_out;

    const size_t smem = SMEM_FLOATS * sizeof(float);   // ~139 KB -> 1 block/SM
    cudaFuncSetAttribute(k_scan, cudaFuncAttributeMaxDynamicSharedMemorySize, (int)smem);

    k_scan<<<128, TPB, smem>>>(adj, has, z, dz,
                               Wih_f, Whh_f, bih_f, bhh_f,
                               Wih_b, Whh_b, bih_b, bhh_b,
                               Wf, bf, Wb, bb,
                               Wu, bu, Wa, ba, Wc, bc, out);
}

// round 16
// speedup vs baseline: 1.0134x; 1.0134x over previous
#include <cuda_runtime.h>
#include <math.h>

#define Bsz   1024
#define Nn    32
#define SE    10
#define OOUT  5
#define IIN   6
#define GPB   16     // samples per block
#define TPB   256    // 8 warps = 4 pairs; pair owns 4 samples; warp owns 30 dims

// ---- shared memory layout (float offsets; all 16B-aligned) ----
#define S_WHH 0        // 180 x 68 = 12240  (adj scratch first, head weights last)
#define S_WIH 12240    // 12240
#define S_WF  24480    // 60 x 84 = 5040
#define S_BIH 29520    // 180
#define S_BF  29700    // 60
#define S_HAS 29760    // 16*32 = 512
#define S_ZD  30272    // 16*20 = 320
#define S_H   30592    // 4 pairs x 2 bufs x 4 samples x 64 = 2048
#define S_RHO 32640    // 16*64 = 1024
#define S_CNT 33664    // 32 ints
#define S_LST 33696    // 32*32 ints
#define SMEM_FLOATS 34720   // ~139 KB -> 1 block/SM

// head-weight staging offsets (reuse S_WHH region after scan)
#define HW_WU 0        // 840
#define HW_BU 840      // 7
#define HW_WA 848      // 600
#define HW_WC 1448     // 120
#define HW_BA 1568     // 5
#define HW_BC 1573     // 1

// ---- device scratch ----
// rho layout is B-MAJOR: [b][n][60]
__device__ float g_rho_f[Bsz * Nn * 60];
__device__ float g_rho_b[Bsz * Nn * 60];
__device__ float g_af[Bsz * 60];
__device__ float g_ab[Bsz * 60];
__device__ float g_gi_f[Nn * Bsz * 180];   // gi cache incl. bih: [node][b][row]
__device__ float g_gi_b[Nn * Bsz * 180];
__device__ int   g_done[64];               // pairwise arrival counters (monotonic)

__device__ __forceinline__ void fma2(unsigned long long& a,
                                     unsigned long long b, unsigned long long c) {
    asm("fma.rn.f32x2 %0,%1,%2,%0;" : "+l"(a) : "l"(b), "l"(c));
}
__device__ __forceinline__ float red2(unsigned long long v) {
    float x, y;
    asm("mov.b64 {%0,%1},%2;" : "=f"(x), "=f"(y) : "l"(v));
    return x + y;
}
__device__ __forceinline__ unsigned long long seed2(float x) {
    return (unsigned long long)__float_as_uint(x);   // (x, +0.0f)
}
__device__ __forceinline__ float sigmf_(float x) {
    return __fdividef(1.0f, 1.0f + __expf(-x));
}
__device__ __forceinline__ float tanhsafe_(float x) {
    float a = fabsf(x);
    float e = __expf(-2.0f * a);
    float t = __fdividef(1.0f - e, 1.0f + e);
    return copysignf(t, x);
}
#define PAIRBAR(id) asm volatile("bar.sync %0, %1;" :: "r"(id), "r"(64) : "memory")

// ============================================================
// Fused scan + heads: 128 blocks (64 fwd, 64 bwd), 16 samples each.
// Warp-PAIR owns 4 samples; warp owns 30 dims (lane = 1 dim, 3 gate rows).
// r-gate Whh row lives in REGISTERS (60 regs; ~218 total, no spill);
// z/n gate rows stream from smem -> weight LDS wavefronts cut 1/3.
// ============================================================
__global__ void __launch_bounds__(TPB) k_scan(
    const unsigned char* __restrict__ adj_raw,
    const float* __restrict__ has, const float* __restrict__ z, const float* __restrict__ dz,
    const float* __restrict__ Wih_f, const float* __restrict__ Whh_f,
    const float* __restrict__ bih_f, const float* __restrict__ bhh_f,
    const float* __restrict__ Wih_b, const float* __restrict__ Whh_b,
    const float* __restrict__ bih_b, const float* __restrict__ bhh_b,
    const float* __restrict__ Wfp, const float* __restrict__ bfp,
    const float* __restrict__ Wbp, const float* __restrict__ bbp,
    const float* __restrict__ Wu, const float* __restrict__ bu,
    const float* __restrict__ Wa, const float* __restrict__ ba,
    const float* __restrict__ Wc, const float* __restrict__ bc,
    float* __restrict__ out)
{
    extern __shared__ __align__(16) float sm[];
    int* smi = (int*)sm;
    const int dir = blockIdx.x >> 6;
    const int pg  = blockIdx.x & 63;
    const int b0  = pg * GPB;
    const float* Wih = dir ? Wih_b : Wih_f;
    const float* Whh = dir ? Whh_b : Whh_f;
    const float* bih = dir ? bih_b : bih_f;
    const float* bhh = dir ? bhh_b : bhh_f;
    const float* Wp  = dir ? Wbp   : Wfp;
    const float* bp  = dir ? bbp   : bfp;
    float* grho = dir ? g_rho_b : g_rho_f;
    float* gic  = dir ? g_gi_b  : g_gi_f;

    const int  tid   = threadIdx.x;
    const int  warp  = tid >> 5;
    const int  lane  = tid & 31;
    const int  pair  = warp >> 1;        // 0..3
    const int  half  = warp & 1;         // 0: dims 0-29, 1: dims 30-59
    const int  sb    = pair * 4;         // pair's sample base
    const int  lpair = half * 32 + lane; // 0..63 within pair
    const int  barid = 1 + pair;
    const bool act   = lane < 30;
    const int  d     = half * 30 + lane; // owned dim (if act)

    // ---- fused prep: decode adj (dtype-ambiguous) + edge lists for this dir
    if (tid < 2) smi[1024 + tid] = 0;
    __syncthreads();
    {
        int f_gt1 = 0, f_off4 = 0;
        for (int t = tid; t < Nn * Nn; t += TPB) {
            unsigned char c = adj_raw[t];
            if (c > 1) f_gt1 = 1;
            if (c == 1 && (t & 3) != 0) f_off4 = 1;
        }
        if (f_gt1)  atomicOr(&smi[1024], 1);
        if (f_off4) atomicOr(&smi[1025], 1);
    }
    __syncthreads();
    {
        const int mode = smi[1024] ? 1 : (smi[1025] ? 0 : 2);
        for (int e = tid; e < Nn * Nn; e += TPB) {
            float v;
            if (mode == 1)      v = ((const float*)adj_raw)[e];
            else if (mode == 2) v = (float)(((const int*)adj_raw)[e]);
            else                v = (float)adj_raw[e];
            sm[e] = v;
        }
    }
    __syncthreads();
    if (tid < Nn) {
        const int i = tid; int c = 0;
        if (dir == 0) {
            for (int j = 0; j < Nn; j++)
                if (sm[j * Nn + i] != 0.0f) smi[S_LST + i * 32 + (c++)] = j;
        } else {
            for (int j = Nn - 1; j >= 0; j--)
                if (sm[i * Nn + j] != 0.0f) smi[S_LST + i * 32 + (c++)] = j;
        }
        smi[S_CNT + i] = c;
    }
    __syncthreads();

    // ---- block-wide weight/bias staging (overwrites adj scratch)
    for (int idx = tid; idx < 10800; idx += TPB) {
        const int r = idx / 60, c = idx - r * 60;
        sm[S_WHH + r * 68 + c] = Whh[idx];
        sm[S_WIH + r * 68 + c] = Wih[idx];
    }
    for (int idx = tid; idx < 4800; idx += TPB)
        sm[S_WF + (idx / 80) * 84 + (idx % 80)] = Wp[idx];
    for (int idx = tid; idx < 180; idx += TPB) sm[S_BIH + idx] = bih[idx];
    for (int idx = tid; idx < 60;  idx += TPB) sm[S_BF + idx]  = bp[idx];
    for (int idx = tid; idx < GPB * Nn; idx += TPB)
        sm[S_HAS + idx] = has[(size_t)(b0 + (idx >> 5)) * Nn + (idx & 31)];
    __syncthreads();

    const float bhh0 = act ? bhh[d]        : 0.0f;
    const float bhh1 = act ? bhh[60 + d]   : 0.0f;
    const float bhh2 = act ? bhh[120 + d]  : 0.0f;
    const float bih0 = act ? sm[S_BIH + d]        : 0.0f;
    const float bih1 = act ? sm[S_BIH + 60 + d]   : 0.0f;
    const float bih2 = act ? sm[S_BIH + 120 + d]  : 0.0f;

    // ---- r-gate weight row -> registers (loop-invariant; 30 ull = 60 regs)
    unsigned long long wr0[30];
    if (act) {
        #pragma unroll
        for (int q = 0; q < 30; q++)
            wr0[q] = *(const unsigned long long*)(sm + S_WHH + d * 68 + 2 * q);
    }

    float* sHp = sm + S_H + pair * 512;   // [buf 2][sample 4][64]
    const float* w1p = sm + S_WHH + (60 + d) * 68;
    const float* w2p = sm + S_WHH + (120 + d) * 68;

    int rp = 0;
    float h_old[4];
    float gi0[4], gi1[4], gi2[4], gn0[4], gn1[4], gn2[4];
    float a0[4], a1[4], a2[4];

    // ================== node scan ==================
    for (int ii = 0; ii < Nn; ii++) {
        const int i = dir ? (Nn - 1 - ii) : ii;

        for (int idx = lpair; idx < 80; idx += 64) {
            const int m = idx / 20, c = idx % 20;
            const size_t base = ((size_t)(b0 + sb + m) * Nn + i) * SE;
            sm[S_ZD + (sb + m) * 20 + c] = (c < SE) ? z[base + c] : dz[base + c - SE];
        }

        const int  cnt = smi[S_CNT + i];
        const int* lst = smi + S_LST + i * 32;

        #pragma unroll
        for (int m = 0; m < 4; m++) h_old[m] = 0.0f;

        if (cnt == 0) {
            if (act) {
                #pragma unroll
                for (int m = 0; m < 4; m++) sHp[rp * 256 + m * 64 + d] = 0.0f;
            }
            PAIRBAR(barid);
        } else {
            if (act) {
                const float* gb = gic + ((size_t)lst[0] * Bsz + b0 + sb) * 180;
                #pragma unroll
                for (int m = 0; m < 4; m++) {
                    gi0[m] = gb[m * 180 + d];
                    gi1[m] = gb[m * 180 + 60 + d];
                    gi2[m] = gb[m * 180 + 120 + d];
                }
            }
            for (int e = 0; e < cnt; e++) {
                const int j = lst[e];
                if (act) {
                    if (e > 0) {
                        unsigned long long A0[4], A1[4], A2[4];
                        #pragma unroll
                        for (int m = 0; m < 4; m++) { A0[m]=0; A1[m]=0; A2[m]=0; }
                        const float* Hb = sHp + rp * 256;
                        #pragma unroll
                        for (int q = 0; q < 15; q++) {
                            const ulonglong2 w1 = *(const ulonglong2*)(w1p + q * 4);
                            const ulonglong2 w2 = *(const ulonglong2*)(w2p + q * 4);
                            #pragma unroll
                            for (int m = 0; m < 4; m++) {
                                const ulonglong2 h = *(const ulonglong2*)(Hb + m * 64 + q * 4);
                                fma2(A0[m], wr0[2*q],   h.x);
                                fma2(A0[m], wr0[2*q+1], h.y);
                                fma2(A1[m], w1.x, h.x); fma2(A1[m], w1.y, h.y);
                                fma2(A2[m], w2.x, h.x); fma2(A2[m], w2.y, h.y);
                            }
                        }
                        #pragma unroll
                        for (int m = 0; m < 4; m++) {
                            a0[m] = red2(A0[m]); a1[m] = red2(A1[m]); a2[m] = red2(A2[m]);
                        }
                    } else {
                        #pragma unroll
                        for (int m = 0; m < 4; m++) { a0[m]=0; a1[m]=0; a2[m]=0; }
                    }
                    if (e + 1 < cnt) {
                        const float* gb = gic + ((size_t)lst[e + 1] * Bsz + b0 + sb) * 180;
                        #pragma unroll
                        for (int m = 0; m < 4; m++) {
                            gn0[m] = gb[m * 180 + d];
                            gn1[m] = gb[m * 180 + 60 + d];
                            gn2[m] = gb[m * 180 + 120 + d];
                        }
                    }
                    #pragma unroll
                    for (int m = 0; m < 4; m++) {
                        const float mask = sm[S_HAS + (sb + m) * 32 + j];
                        const float r  = sigmf_(a0[m] + gi0[m] + bhh0);
                        const float u  = sigmf_(a1[m] + gi1[m] + bhh1);
                        const float nv = tanhsafe_(gi2[m] + r * (a2[m] + bhh2));
                        const float ho = h_old[m];
                        const float h2 = (1.0f - u) * nv + u * ho;
                        const float hn = ho + mask * (h2 - ho);
                        h_old[m] = hn;
                        sHp[(1 - rp) * 256 + m * 64 + d] = hn;
                    }
                    if (e + 1 < cnt) {
                        #pragma unroll
                        for (int m = 0; m < 4; m++) {
                            gi0[m]=gn0[m]; gi1[m]=gn1[m]; gi2[m]=gn2[m];
                        }
                    }
                }
                PAIRBAR(barid);
                rp ^= 1;
            }
        }

        // ---- projection
        if (act) {
            const ulonglong2* Wr = (const ulonglong2*)(sm + S_WF + d * 84);
            #pragma unroll
            for (int m = 0; m < 4; m++) {
                unsigned long long acc = seed2(sm[S_BF + d]);
                const ulonglong2* Hh = (const ulonglong2*)(sHp + rp * 256 + m * 64);
                #pragma unroll
                for (int q = 0; q < 15; q++) {
                    const ulonglong2 w = Wr[q], h = Hh[q];
                    fma2(acc, w.x, h.x); fma2(acc, w.y, h.y);
                }
                const ulonglong2* Zd = (const ulonglong2*)(sm + S_ZD + (sb + m) * 20);
                #pragma unroll
                for (int q = 0; q < 5; q++) {
                    const ulonglong2 w = Wr[15 + q], x = Zd[q];
                    fma2(acc, w.x, x.x); fma2(acc, w.y, x.y);
                }
                float val = red2(acc);
                if (dir == 0) val = tanhsafe_(val);
                sm[S_RHO + (sb + m) * 64 + d] = val;
                grho[((size_t)(b0 + sb + m) * Nn + i) * 60 + d] = val;   // b-major
            }
        }
        PAIRBAR(barid);

        // ---- gi for node i
        if (act) {
            unsigned long long A0[4], A1[4], A2[4];
            #pragma unroll
            for (int m = 0; m < 4; m++) {
                A0[m] = seed2(bih0); A1[m] = seed2(bih1); A2[m] = seed2(bih2);
            }
            const float* u0p = sm + S_WIH + d * 68;
            const float* u1p = sm + S_WIH + (60 + d) * 68;
            const float* u2p = sm + S_WIH + (120 + d) * 68;
            const float* Rb = sm + S_RHO + sb * 64;
            #pragma unroll
            for (int q = 0; q < 15; q++) {
                const ulonglong2 w0 = *(const ulonglong2*)(u0p + q * 4);
                const ulonglong2 w1 = *(const ulonglong2*)(u1p + q * 4);
                const ulonglong2 w2 = *(const ulonglong2*)(u2p + q * 4);
                #pragma unroll
                for (int m = 0; m < 4; m++) {
                    const ulonglong2 rv = *(const ulonglong2*)(Rb + m * 64 + q * 4);
                    fma2(A0[m], w0.x, rv.x); fma2(A0[m], w0.y, rv.y);
                    fma2(A1[m], w1.x, rv.x); fma2(A1[m], w1.y, rv.y);
                    fma2(A2[m], w2.x, rv.x); fma2(A2[m], w2.y, rv.y);
                }
            }
            #pragma unroll
            for (int m = 0; m < 4; m++) {
                float* gp = gic + ((size_t)i * Bsz + b0 + sb + m) * 180;
                gp[d]       = red2(A0[m]);
                gp[60 + d]  = red2(A1[m]);
                gp[120 + d] = red2(A2[m]);
            }
        }
    }

    // ================== alpha scan ==================
    #pragma unroll
    for (int m = 0; m < 4; m++) h_old[m] = 0.0f;
    const int steps = dir ? IIN : OOUT;
    for (int s = 0; s < steps; s++) {
        const int i = dir ? (IIN - 1 - s) : (Nn - OOUT + s);
        if (act) {
            const float* gb = gic + ((size_t)i * Bsz + b0 + sb) * 180;
            #pragma unroll
            for (int m = 0; m < 4; m++) {
                gi0[m] = gb[m * 180 + d];
                gi1[m] = gb[m * 180 + 60 + d];
                gi2[m] = gb[m * 180 + 120 + d];
            }
            if (s > 0) {
                unsigned long long A0[4], A1[4], A2[4];
                #pragma unroll
                for (int m = 0; m < 4; m++) { A0[m]=0; A1[m]=0; A2[m]=0; }
                const float* Hb = sHp + rp * 256;
                #pragma unroll
                for (int q = 0; q < 15; q++) {
                    const ulonglong2 w1 = *(const ulonglong2*)(w1p + q * 4);
                    const ulonglong2 w2 = *(const ulonglong2*)(w2p + q * 4);
                    #pragma unroll
                    for (int m = 0; m < 4; m++) {
                        const ulonglong2 h = *(const ulonglong2*)(Hb + m * 64 + q * 4);
                        fma2(A0[m], wr0[2*q],   h.x);
                        fma2(A0[m], wr0[2*q+1], h.y);
                        fma2(A1[m], w1.x, h.x); fma2(A1[m], w1.y, h.y);
                        fma2(A2[m], w2.x, h.x); fma2(A2[m], w2.y, h.y);
                    }
                }
                #pragma unroll
                for (int m = 0; m < 4; m++) {
                    a0[m] = red2(A0[m]); a1[m] = red2(A1[m]); a2[m] = red2(A2[m]);
                }
            } else {
                #pragma unroll
                for (int m = 0; m < 4; m++) { a0[m]=0; a1[m]=0; a2[m]=0; }
            }
            #pragma unroll
            for (int m = 0; m < 4; m++) {
                const float mask = sm[S_HAS + (sb + m) * 32 + i];
                const float r  = sigmf_(a0[m] + gi0[m] + bhh0);
                const float u  = sigmf_(a1[m] + gi1[m] + bhh1);
                const float nv = tanhsafe_(gi2[m] + r * (a2[m] + bhh2));
                const float ho = h_old[m];
                const float h2 = (1.0f - u) * nv + u * ho;
                const float hn = ho + mask * (h2 - ho);
                h_old[m] = hn;
                sHp[(1 - rp) * 256 + m * 64 + d] = hn;
            }
        }
        PAIRBAR(barid);
        rp ^= 1;
    }
    if (act) {
        float* ga = dir ? g_ab : g_af;
        #pragma unroll
        for (int m = 0; m < 4; m++)
            ga[(size_t)(b0 + sb + m) * 60 + d] = h_old[m];
    }

    // ================== pairwise handshake + fused heads ==================
    __threadfence();
    __syncthreads();
    if (tid == 0) {
        const int old = atomicAdd(&g_done[pg], 1);
        const int target = (old & ~1) + 2;        // replay-safe round target
        while (*(volatile int*)&g_done[pg] < target) { }
        __threadfence();
    }
    __syncthreads();

    for (int idx = tid; idx < 840; idx += TPB) sm[HW_WU + idx] = Wu[idx];
    for (int idx = tid; idx < 600; idx += TPB) sm[HW_WA + idx] = Wa[idx];
    for (int idx = tid; idx < 120; idx += TPB) sm[HW_WC + idx] = Wc[idx];
    if (tid < 7)  sm[HW_BU + tid] = bu[tid];
    if (tid < 5)  sm[HW_BA + tid] = ba[tid];
    if (tid == 0) sm[HW_BC] = bc[0];
    __syncthreads();

    // ---- roles: this block handles 8 samples (fwd: first 8; bwd: last 8)
    {
        const int m8 = tid >> 5;                 // 0..7
        const int n  = tid & 31;
        const int b  = b0 + dir * 8 + m8;

        float acc[7];
        #pragma unroll
        for (int r = 0; r < 7; r++) acc[r] = sm[HW_BU + r];

        const float4* rf = (const float4*)(g_rho_f + ((size_t)b * Nn + n) * 60);
        const float4* rb = (const float4*)(g_rho_b + ((size_t)b * Nn + n) * 60);
        #pragma unroll
        for (int q = 0; q < 15; q++) {
            const float4 f = rf[q];
            #pragma unroll
            for (int r = 0; r < 7; r++) {
                const float4 w = *(const float4*)(sm + HW_WU + r * 120 + q * 4);
                acc[r] += w.x*f.x + w.y*f.y + w.z*f.z + w.w*f.w;
            }
        }
        #pragma unroll
        for (int q = 0; q < 15; q++) {
            const float4 f = rb[q];
            #pragma unroll
            for (int r = 0; r < 7; r++) {
                const float4 w = *(const float4*)(sm + HW_WU + r * 120 + 60 + q * 4);
                acc[r] += w.x*f.x + w.y*f.y + w.z*f.z + w.w*f.w;
            }
        }
        const float msk = sm[S_HAS + (dir * 8 + m8) * 32 + n];
        float l[7], mx = -1e30f;
        #pragma unroll
        for (int r = 0; r < 7; r++) { l[r] = (msk != 0.0f) ? acc[r] : -60.0f; mx = fmaxf(mx, l[r]); }
        float s = 0.0f;
        #pragma unroll
        for (int r = 0; r < 7; r++) { l[r] = __expf(l[r] - mx); s += l[r]; }
        const float inv = __fdividef(1.0f, s);
        float* ro = out + 5120;
        #pragma unroll
        for (int r = 0; r < 7; r++) ro[((size_t)b * 7 + r) * 32 + n] = l[r] * inv;
    }

    // ---- instr + value: bwd block only, 4 lanes per sample (tid < 64)
    if (dir == 1 && tid < 64) {
        const int b    = b0 + (tid >> 2);
        const int lane4 = tid & 3;

        float acc[6];
        #pragma unroll
        for (int a = 0; a < 6; a++) acc[a] = 0.0f;

        const float4* af = (const float4*)(g_af + (size_t)b * 60);
        const float4* ab = (const float4*)(g_ab + (size_t)b * 60);
        for (int q = lane4; q < 30; q += 4) {
            const float4 f = (q < 15) ? af[q] : ab[q - 15];
            #pragma unroll
            for (int a = 0; a < 5; a++) {
                const float4 w = *(const float4*)(sm + HW_WA + a * 120 + q * 4);
                acc[a] += w.x*f.x + w.y*f.y + w.z*f.z + w.w*f.w;
            }
            const float4 wc = *(const float4*)(sm + HW_WC + q * 4);
            acc[5] += wc.x*f.x + wc.y*f.y + wc.z*f.z + wc.w*f.w;
        }
        #pragma unroll
        for (int off = 1; off < 4; off <<= 1) {
            #pragma unroll
            for (int a = 0; a < 6; a++)
                acc[a] += __shfl_xor_sync(0xffffffffu, acc[a], off);
        }
        if (lane4 == 0) {
            float l[5], mx = -1e30f;
            #pragma unroll
            for (int a = 0; a < 5; a++) { l[a] = acc[a] + sm[HW_BA + a]; mx = fmaxf(mx, l[a]); }
            float s = 0.0f;
            #pragma unroll
            for (int a = 0; a < 5; a++) { l[a] = __expf(l[a] - mx); s += l[a]; }
            const float inv = __fdividef(1.0f, s);
            #pragma unroll
            for (int a = 0; a < 5; a++) out[b * 5 + a] = l[a] * inv;
            out[5120 + Bsz * 7 * Nn + b] = acc[5] + sm[HW_BC];   // value @ 234496
        }
    }
}

// ============================================================
extern "C" void kernel_launch(void* const* d_in, const int* in_sizes, int n_in,
                              void* d_out, int out_size)
{
    const float* has   = (const float*)d_in[0];
    const float* z     = (const float*)d_in[1];
    const float* dz    = (const float*)d_in[2];
    const unsigned char* adj = (const unsigned char*)d_in[3];
    const float* Wih_f = (const float*)d_in[4];
    const float* Whh_f = (const float*)d_in[5];
    const float* bih_f = (const float*)d_in[6];
    const float* bhh_f = (const float*)d_in[7];
    const float* Wih_b = (const float*)d_in[8];
    const float* Whh_b = (const float*)d_in[9];
    const float* bih_b = (const float*)d_in[10];
    const float* bhh_b = (const float*)d_in[11];
    const float* Wf    = (const float*)d_in[12];
    const float* bf    = (const float*)d_in[13];
    const float* Wb    = (const float*)d_in[14];
    const float* bb    = (const float*)d_in[15];
    const float* Wa    = (const float*)d_in[16];
    const float* ba    = (const float*)d_in[17];
    const float* Wc    = (const float*)d_in[18];
    const float* bc    = (const float*)d_in[19];
    const float* Wu    = (const float*)d_in[20];
    const float* bu    = (const float*)d_in[21];
    float* out = (float*)d_out;

    const size_t smem = SMEM_FLOATS * sizeof(float);   // ~139 KB -> 1 block/SM
    cudaFuncSetAttribute(k_scan, cudaFuncAttributeMaxDynamicSharedMemorySize, (int)smem);

    k_scan<<<128, TPB, smem>>>(adj, has, z, dz,
                               Wih_f, Whh_f, bih_f, bhh_f,
                               Wih_b, Whh_b, bih_b, bhh_b,
                               Wf, bf, Wb, bb,
                               Wu, bu, Wa, ba, Wc, bc, out);
}

// round 17
// speedup vs baseline: 1.0904x; 1.0760x over previous
#include <cuda_runtime.h>
#include <math.h>

#define Bsz   1024
#define Nn    32
#define SE    10
#define OOUT  5
#define IIN   6
#define GPB   16     // samples per block
#define TPB   256    // 8 warps = 4 pairs; pair owns 4 samples; warp owns 30 dims

// ---- shared memory layout (float offsets; all 16B-aligned) ----
#define S_WHH 0        // 180 x 68 = 12240  (adj scratch first, head weights last)
#define S_WIH 12240    // 12240
#define S_WF  24480    // 60 x 84 = 5040
#define S_BIH 29520    // 180
#define S_BF  29700    // 60
#define S_HAS 29760    // 16*32 = 512
#define S_ZD  30272    // 16*20 = 320
#define S_H   30592    // 4 pairs x 2 bufs x 4 samples x 64 = 2048
#define S_RHO 32640    // 16*64 = 1024
#define S_CNT 33664    // 32 ints
#define S_LST 33696    // 32*32 ints
#define SMEM_FLOATS 34720   // ~139 KB -> 1 block/SM

// head-weight staging offsets (reuse S_WHH region after scan)
#define HW_WU 0        // 840
#define HW_BU 840      // 7
#define HW_WA 848      // 600
#define HW_WC 1448     // 120
#define HW_BA 1568     // 5
#define HW_BC 1573     // 1

// ---- device scratch ----
// rho layout is B-MAJOR: [b][n][60]
__device__ float g_rho_f[Bsz * Nn * 60];
__device__ float g_rho_b[Bsz * Nn * 60];
__device__ float g_af[Bsz * 60];
__device__ float g_ab[Bsz * 60];
__device__ float g_gi_f[Nn * Bsz * 180];   // gi cache incl. bih: [node][b][row]
__device__ float g_gi_b[Nn * Bsz * 180];
__device__ int   g_done[64];               // pairwise arrival counters (monotonic)

__device__ __forceinline__ void fma2(unsigned long long& a,
                                     unsigned long long b, unsigned long long c) {
    asm("fma.rn.f32x2 %0,%1,%2,%0;" : "+l"(a) : "l"(b), "l"(c));
}
__device__ __forceinline__ float red2(unsigned long long v) {
    float x, y;
    asm("mov.b64 {%0,%1},%2;" : "=f"(x), "=f"(y) : "l"(v));
    return x + y;
}
__device__ __forceinline__ unsigned long long seed2(float x) {
    return (unsigned long long)__float_as_uint(x);   // (x, +0.0f)
}
__device__ __forceinline__ float sigmf_(float x) {
    return __fdividef(1.0f, 1.0f + __expf(-x));
}
__device__ __forceinline__ float tanhsafe_(float x) {
    float a = fabsf(x);
    float e = __expf(-2.0f * a);
    float t = __fdividef(1.0f - e, 1.0f + e);
    return copysignf(t, x);
}
#define PAIRBAR(id) asm volatile("bar.sync %0, %1;" :: "r"(id), "r"(64) : "memory")

// ============================================================
// Fused scan + heads: 128 blocks (64 fwd, 64 bwd), 16 samples each.
// Warp-PAIR owns 4 samples; warp owns 30 dims (lane = 1 dim, 3 gate rows).
// r-gate Whh row fully in registers; z-gate row first 24 floats in
// registers (regs ~241, under cap); n row + z tail stream from smem.
// Next node's first-edge gi prefetched during the gi phase.
// ============================================================
__global__ void __launch_bounds__(TPB) k_scan(
    const unsigned char* __restrict__ adj_raw,
    const float* __restrict__ has, const float* __restrict__ z, const float* __restrict__ dz,
    const float* __restrict__ Wih_f, const float* __restrict__ Whh_f,
    const float* __restrict__ bih_f, const float* __restrict__ bhh_f,
    const float* __restrict__ Wih_b, const float* __restrict__ Whh_b,
    const float* __restrict__ bih_b, const float* __restrict__ bhh_b,
    const float* __restrict__ Wfp, const float* __restrict__ bfp,
    const float* __restrict__ Wbp, const float* __restrict__ bbp,
    const float* __restrict__ Wu, const float* __restrict__ bu,
    const float* __restrict__ Wa, const float* __restrict__ ba,
    const float* __restrict__ Wc, const float* __restrict__ bc,
    float* __restrict__ out)
{
    extern __shared__ __align__(16) float sm[];
    int* smi = (int*)sm;
    const int dir = blockIdx.x >> 6;
    const int pg  = blockIdx.x & 63;
    const int b0  = pg * GPB;
    const float* Wih = dir ? Wih_b : Wih_f;
    const float* Whh = dir ? Whh_b : Whh_f;
    const float* bih = dir ? bih_b : bih_f;
    const float* bhh = dir ? bhh_b : bhh_f;
    const float* Wp  = dir ? Wbp   : Wfp;
    const float* bp  = dir ? bbp   : bfp;
    float* grho = dir ? g_rho_b : g_rho_f;
    float* gic  = dir ? g_gi_b  : g_gi_f;

    const int  tid   = threadIdx.x;
    const int  warp  = tid >> 5;
    const int  lane  = tid & 31;
    const int  pair  = warp >> 1;        // 0..3
    const int  half  = warp & 1;         // 0: dims 0-29, 1: dims 30-59
    const int  sb    = pair * 4;         // pair's sample base
    const int  lpair = half * 32 + lane; // 0..63 within pair
    const int  barid = 1 + pair;
    const bool act   = lane < 30;
    const int  d     = half * 30 + lane; // owned dim (if act)

    // ---- fused prep: decode adj (dtype-ambiguous) + edge lists for this dir
    if (tid < 2) smi[1024 + tid] = 0;
    __syncthreads();
    {
        int f_gt1 = 0, f_off4 = 0;
        for (int t = tid; t < Nn * Nn; t += TPB) {
            unsigned char c = adj_raw[t];
            if (c > 1) f_gt1 = 1;
            if (c == 1 && (t & 3) != 0) f_off4 = 1;
        }
        if (f_gt1)  atomicOr(&smi[1024], 1);
        if (f_off4) atomicOr(&smi[1025], 1);
    }
    __syncthreads();
    {
        const int mode = smi[1024] ? 1 : (smi[1025] ? 0 : 2);
        for (int e = tid; e < Nn * Nn; e += TPB) {
            float v;
            if (mode == 1)      v = ((const float*)adj_raw)[e];
            else if (mode == 2) v = (float)(((const int*)adj_raw)[e]);
            else                v = (float)adj_raw[e];
            sm[e] = v;
        }
    }
    __syncthreads();
    if (tid < Nn) {
        const int i = tid; int c = 0;
        if (dir == 0) {
            for (int j = 0; j < Nn; j++)
                if (sm[j * Nn + i] != 0.0f) smi[S_LST + i * 32 + (c++)] = j;
        } else {
            for (int j = Nn - 1; j >= 0; j--)
                if (sm[i * Nn + j] != 0.0f) smi[S_LST + i * 32 + (c++)] = j;
        }
        smi[S_CNT + i] = c;
    }
    __syncthreads();

    // ---- block-wide weight/bias staging (overwrites adj scratch)
    for (int idx = tid; idx < 10800; idx += TPB) {
        const int r = idx / 60, c = idx - r * 60;
        sm[S_WHH + r * 68 + c] = Whh[idx];
        sm[S_WIH + r * 68 + c] = Wih[idx];
    }
    for (int idx = tid; idx < 4800; idx += TPB)
        sm[S_WF + (idx / 80) * 84 + (idx % 80)] = Wp[idx];
    for (int idx = tid; idx < 180; idx += TPB) sm[S_BIH + idx] = bih[idx];
    for (int idx = tid; idx < 60;  idx += TPB) sm[S_BF + idx]  = bp[idx];
    for (int idx = tid; idx < GPB * Nn; idx += TPB)
        sm[S_HAS + idx] = has[(size_t)(b0 + (idx >> 5)) * Nn + (idx & 31)];
    __syncthreads();

    const float bhh0 = act ? bhh[d]        : 0.0f;
    const float bhh1 = act ? bhh[60 + d]   : 0.0f;
    const float bhh2 = act ? bhh[120 + d]  : 0.0f;
    const float bih0 = act ? sm[S_BIH + d]        : 0.0f;
    const float bih1 = act ? sm[S_BIH + 60 + d]   : 0.0f;
    const float bih2 = act ? sm[S_BIH + 120 + d]  : 0.0f;

    // ---- r-gate weight row -> registers (30 ull); z-row first 24 floats (12 ull)
    unsigned long long wr0[30];
    unsigned long long wz0[12];
    if (act) {
        #pragma unroll
        for (int q = 0; q < 30; q++)
            wr0[q] = *(const unsigned long long*)(sm + S_WHH + d * 68 + 2 * q);
        #pragma unroll
        for (int q = 0; q < 12; q++)
            wz0[q] = *(const unsigned long long*)(sm + S_WHH + (60 + d) * 68 + 2 * q);
    }

    float* sHp = sm + S_H + pair * 512;   // [buf 2][sample 4][64]
    const float* w1p = sm + S_WHH + (60 + d) * 68;
    const float* w2p = sm + S_WHH + (120 + d) * 68;

    int rp = 0;
    float h_old[4];
    float gi0[4], gi1[4], gi2[4], gn0[4], gn1[4], gn2[4];
    float a0[4], a1[4], a2[4];

    // ---- prologue: gi invariant for the first node (dead for triu adj)
    {
        const int i1 = dir ? (Nn - 1) : 0;
        if (act && smi[S_CNT + i1] > 0) {
            const int j0 = smi[S_LST + i1 * 32];
            const float* gb = gic + ((size_t)j0 * Bsz + b0 + sb) * 180;
            #pragma unroll
            for (int m = 0; m < 4; m++) {
                gi0[m] = gb[m * 180 + d];
                gi1[m] = gb[m * 180 + 60 + d];
                gi2[m] = gb[m * 180 + 120 + d];
            }
        }
    }

    // ================== node scan ==================
    for (int ii = 0; ii < Nn; ii++) {
        const int i = dir ? (Nn - 1 - ii) : ii;

        for (int idx = lpair; idx < 80; idx += 64) {
            const int m = idx / 20, c = idx % 20;
            const size_t base = ((size_t)(b0 + sb + m) * Nn + i) * SE;
            sm[S_ZD + (sb + m) * 20 + c] = (c < SE) ? z[base + c] : dz[base + c - SE];
        }

        const int  cnt = smi[S_CNT + i];
        const int* lst = smi + S_LST + i * 32;

        #pragma unroll
        for (int m = 0; m < 4; m++) h_old[m] = 0.0f;

        if (cnt == 0) {
            if (act) {
                #pragma unroll
                for (int m = 0; m < 4; m++) sHp[rp * 256 + m * 64 + d] = 0.0f;
            }
            PAIRBAR(barid);
        } else {
            // gi0..2 already hold gi(lst[0]) -- prefetched in prior gi phase
            for (int e = 0; e < cnt; e++) {
                const int j = lst[e];
                if (act) {
                    if (e > 0) {
                        unsigned long long A0[4], A1[4], A2[4];
                        #pragma unroll
                        for (int m = 0; m < 4; m++) { A0[m]=0; A1[m]=0; A2[m]=0; }
                        const float* Hb = sHp + rp * 256;
                        #pragma unroll
                        for (int q = 0; q < 6; q++) {        // z from registers
                            const ulonglong2 w2 = *(const ulonglong2*)(w2p + q * 4);
                            #pragma unroll
                            for (int m = 0; m < 4; m++) {
                                const ulonglong2 h = *(const ulonglong2*)(Hb + m * 64 + q * 4);
                                fma2(A0[m], wr0[2*q],   h.x);
                                fma2(A0[m], wr0[2*q+1], h.y);
                                fma2(A1[m], wz0[2*q],   h.x);
                                fma2(A1[m], wz0[2*q+1], h.y);
                                fma2(A2[m], w2.x, h.x); fma2(A2[m], w2.y, h.y);
                            }
                        }
                        #pragma unroll
                        for (int q = 6; q < 15; q++) {       // z tail from smem
                            const ulonglong2 w1 = *(const ulonglong2*)(w1p + q * 4);
                            const ulonglong2 w2 = *(const ulonglong2*)(w2p + q * 4);
                            #pragma unroll
                            for (int m = 0; m < 4; m++) {
                                const ulonglong2 h = *(const ulonglong2*)(Hb + m * 64 + q * 4);
                                fma2(A0[m], wr0[2*q],   h.x);
                                fma2(A0[m], wr0[2*q+1], h.y);
                                fma2(A1[m], w1.x, h.x); fma2(A1[m], w1.y, h.y);
                                fma2(A2[m], w2.x, h.x); fma2(A2[m], w2.y, h.y);
                            }
                        }
                        #pragma unroll
                        for (int m = 0; m < 4; m++) {
                            a0[m] = red2(A0[m]); a1[m] = red2(A1[m]); a2[m] = red2(A2[m]);
                        }
                    } else {
                        #pragma unroll
                        for (int m = 0; m < 4; m++) { a0[m]=0; a1[m]=0; a2[m]=0; }
                    }
                    if (e + 1 < cnt) {
                        const float* gb = gic + ((size_t)lst[e + 1] * Bsz + b0 + sb) * 180;
                        #pragma unroll
                        for (int m = 0; m < 4; m++) {
                            gn0[m] = gb[m * 180 + d];
                            gn1[m] = gb[m * 180 + 60 + d];
                            gn2[m] = gb[m * 180 + 120 + d];
                        }
                    }
                    #pragma unroll
                    for (int m = 0; m < 4; m++) {
                        const float mask = sm[S_HAS + (sb + m) * 32 + j];
                        const float r  = sigmf_(a0[m] + gi0[m] + bhh0);
                        const float u  = sigmf_(a1[m] + gi1[m] + bhh1);
                        const float nv = tanhsafe_(gi2[m] + r * (a2[m] + bhh2));
                        const float ho = h_old[m];
                        const float h2 = (1.0f - u) * nv + u * ho;
                        const float hn = ho + mask * (h2 - ho);
                        h_old[m] = hn;
                        sHp[(1 - rp) * 256 + m * 64 + d] = hn;
                    }
                    if (e + 1 < cnt) {
                        #pragma unroll
                        for (int m = 0; m < 4; m++) {
                            gi0[m]=gn0[m]; gi1[m]=gn1[m]; gi2[m]=gn2[m];
                        }
                    }
                }
                PAIRBAR(barid);
                rp ^= 1;
            }
        }

        // ---- projection
        if (act) {
            const ulonglong2* Wr = (const ulonglong2*)(sm + S_WF + d * 84);
            #pragma unroll
            for (int m = 0; m < 4; m++) {
                unsigned long long acc = seed2(sm[S_BF + d]);
                const ulonglong2* Hh = (const ulonglong2*)(sHp + rp * 256 + m * 64);
                #pragma unroll
                for (int q = 0; q < 15; q++) {
                    const ulonglong2 w = Wr[q], h = Hh[q];
                    fma2(acc, w.x, h.x); fma2(acc, w.y, h.y);
                }
                const ulonglong2* Zd = (const ulonglong2*)(sm + S_ZD + (sb + m) * 20);
                #pragma unroll
                for (int q = 0; q < 5; q++) {
                    const ulonglong2 w = Wr[15 + q], x = Zd[q];
                    fma2(acc, w.x, x.x); fma2(acc, w.y, x.y);
                }
                float val = red2(acc);
                if (dir == 0) val = tanhsafe_(val);
                sm[S_RHO + (sb + m) * 64 + d] = val;
                grho[((size_t)(b0 + sb + m) * Nn + i) * 60 + d] = val;   // b-major
            }
        }
        PAIRBAR(barid);

        // ---- gi for node i + prefetch next node's first-edge gi
        if (act) {
            unsigned long long A0[4], A1[4], A2[4];
            #pragma unroll
            for (int m = 0; m < 4; m++) {
                A0[m] = seed2(bih0); A1[m] = seed2(bih1); A2[m] = seed2(bih2);
            }
            const float* u0p = sm + S_WIH + d * 68;
            const float* u1p = sm + S_WIH + (60 + d) * 68;
            const float* u2p = sm + S_WIH + (120 + d) * 68;
            const float* Rb = sm + S_RHO + sb * 64;
            #pragma unroll
            for (int q = 0; q < 15; q++) {
                const ulonglong2 w0 = *(const ulonglong2*)(u0p + q * 4);
                const ulonglong2 w1 = *(const ulonglong2*)(u1p + q * 4);
                const ulonglong2 w2 = *(const ulonglong2*)(u2p + q * 4);
                #pragma unroll
                for (int m = 0; m < 4; m++) {
                    const ulonglong2 rv = *(const ulonglong2*)(Rb + m * 64 + q * 4);
                    fma2(A0[m], w0.x, rv.x); fma2(A0[m], w0.y, rv.y);
                    fma2(A1[m], w1.x, rv.x); fma2(A1[m], w1.y, rv.y);
                    fma2(A2[m], w2.x, rv.x); fma2(A2[m], w2.y, rv.y);
                }
            }
            // reuse a0..a2 as the reduced gi values
            #pragma unroll
            for (int m = 0; m < 4; m++) {
                a0[m] = red2(A0[m]); a1[m] = red2(A1[m]); a2[m] = red2(A2[m]);
                float* gp = gic + ((size_t)i * Bsz + b0 + sb + m) * 180;
                gp[d]       = a0[m];
                gp[60 + d]  = a1[m];
                gp[120 + d] = a2[m];
            }
            // prefetch gi for next node's first edge into gi0..2
            if (ii + 1 < Nn) {
                const int i2 = dir ? (i - 1) : (i + 1);
                if (smi[S_CNT + i2] > 0) {
                    const int j0 = smi[S_LST + i2 * 32];
                    if (j0 == i) {
                        #pragma unroll
                        for (int m = 0; m < 4; m++) {
                            gi0[m] = a0[m]; gi1[m] = a1[m]; gi2[m] = a2[m];
                        }
                    } else {
                        const float* gb = gic + ((size_t)j0 * Bsz + b0 + sb) * 180;
                        #pragma unroll
                        for (int m = 0; m < 4; m++) {
                            gi0[m] = gb[m * 180 + d];
                            gi1[m] = gb[m * 180 + 60 + d];
                            gi2[m] = gb[m * 180 + 120 + d];
                        }
                    }
                }
            }
        }
    }

    // ================== alpha scan ==================
    #pragma unroll
    for (int m = 0; m < 4; m++) h_old[m] = 0.0f;
    const int steps = dir ? IIN : OOUT;
    for (int s = 0; s < steps; s++) {
        const int i = dir ? (IIN - 1 - s) : (Nn - OOUT + s);
        if (act) {
            const float* gb = gic + ((size_t)i * Bsz + b0 + sb) * 180;
            #pragma unroll
            for (int m = 0; m < 4; m++) {
                gi0[m] = gb[m * 180 + d];
                gi1[m] = gb[m * 180 + 60 + d];
                gi2[m] = gb[m * 180 + 120 + d];
            }
            if (s > 0) {
                unsigned long long A0[4], A1[4], A2[4];
                #pragma unroll
                for (int m = 0; m < 4; m++) { A0[m]=0; A1[m]=0; A2[m]=0; }
                const float* Hb = sHp + rp * 256;
                #pragma unroll
                for (int q = 0; q < 6; q++) {
                    const ulonglong2 w2 = *(const ulonglong2*)(w2p + q * 4);
                    #pragma unroll
                    for (int m = 0; m < 4; m++) {
                        const ulonglong2 h = *(const ulonglong2*)(Hb + m * 64 + q * 4);
                        fma2(A0[m], wr0[2*q],   h.x);
                        fma2(A0[m], wr0[2*q+1], h.y);
                        fma2(A1[m], wz0[2*q],   h.x);
                        fma2(A1[m], wz0[2*q+1], h.y);
                        fma2(A2[m], w2.x, h.x); fma2(A2[m], w2.y, h.y);
                    }
                }
                #pragma unroll
                for (int q = 6; q < 15; q++) {
                    const ulonglong2 w1 = *(const ulonglong2*)(w1p + q * 4);
                    const ulonglong2 w2 = *(const ulonglong2*)(w2p + q * 4);
                    #pragma unroll
                    for (int m = 0; m < 4; m++) {
                        const ulonglong2 h = *(const ulonglong2*)(Hb + m * 64 + q * 4);
                        fma2(A0[m], wr0[2*q],   h.x);
                        fma2(A0[m], wr0[2*q+1], h.y);
                        fma2(A1[m], w1.x, h.x); fma2(A1[m], w1.y, h.y);
                        fma2(A2[m], w2.x, h.x); fma2(A2[m], w2.y, h.y);
                    }
                }
                #pragma unroll
                for (int m = 0; m < 4; m++) {
                    a0[m] = red2(A0[m]); a1[m] = red2(A1[m]); a2[m] = red2(A2[m]);
                }
            } else {
                #pragma unroll
                for (int m = 0; m < 4; m++) { a0[m]=0; a1[m]=0; a2[m]=0; }
            }
            #pragma unroll
            for (int m = 0; m < 4; m++) {
                const float mask = sm[S_HAS + (sb + m) * 32 + i];
                const float r  = sigmf_(a0[m] + gi0[m] + bhh0);
                const float u  = sigmf_(a1[m] + gi1[m] + bhh1);
                const float nv = tanhsafe_(gi2[m] + r * (a2[m] + bhh2));
                const float ho = h_old[m];
                const float h2 = (1.0f - u) * nv + u * ho;
                const float hn = ho + mask * (h2 - ho);
                h_old[m] = hn;
                sHp[(1 - rp) * 256 + m * 64 + d] = hn;
            }
        }
        PAIRBAR(barid);
        rp ^= 1;
    }
    if (act) {
        float* ga = dir ? g_ab : g_af;
        #pragma unroll
        for (int m = 0; m < 4; m++)
            ga[(size_t)(b0 + sb + m) * 60 + d] = h_old[m];
    }

    // ================== pairwise handshake + fused heads ==================
    __threadfence();
    __syncthreads();
    if (tid == 0) {
        const int old = atomicAdd(&g_done[pg], 1);
        const int target = (old & ~1) + 2;        // replay-safe round target
        while (*(volatile int*)&g_done[pg] < target) { }
        __threadfence();
    }
    __syncthreads();

    for (int idx = tid; idx < 840; idx += TPB) sm[HW_WU + idx] = Wu[idx];
    for (int idx = tid; idx < 600; idx += TPB) sm[HW_WA + idx] = Wa[idx];
    for (int idx = tid; idx < 120; idx += TPB) sm[HW_WC + idx] = Wc[idx];
    if (tid < 7)  sm[HW_BU + tid] = bu[tid];
    if (tid < 5)  sm[HW_BA + tid] = ba[tid];
    if (tid == 0) sm[HW_BC] = bc[0];
    __syncthreads();

    // ---- roles: this block handles 8 samples (fwd: first 8; bwd: last 8)
    {
        const int m8 = tid >> 5;                 // 0..7
        const int n  = tid & 31;
        const int b  = b0 + dir * 8 + m8;

        float acc[7];
        #pragma unroll
        for (int r = 0; r < 7; r++) acc[r] = sm[HW_BU + r];

        const float4* rf = (const float4*)(g_rho_f + ((size_t)b * Nn + n) * 60);
        const float4* rb = (const float4*)(g_rho_b + ((size_t)b * Nn + n) * 60);
        #pragma unroll
        for (int q = 0; q < 15; q++) {
            const float4 f = rf[q];
            #pragma unroll
            for (int r = 0; r < 7; r++) {
                const float4 w = *(const float4*)(sm + HW_WU + r * 120 + q * 4);
                acc[r] += w.x*f.x + w.y*f.y + w.z*f.z + w.w*f.w;
            }
        }
        #pragma unroll
        for (int q = 0; q < 15; q++) {
            const float4 f = rb[q];
            #pragma unroll
            for (int r = 0; r < 7; r++) {
                const float4 w = *(const float4*)(sm + HW_WU + r * 120 + 60 + q * 4);
                acc[r] += w.x*f.x + w.y*f.y + w.z*f.z + w.w*f.w;
            }
        }
        const float msk = sm[S_HAS + (dir * 8 + m8) * 32 + n];
        float l[7], mx = -1e30f;
        #pragma unroll
        for (int r = 0; r < 7; r++) { l[r] = (msk != 0.0f) ? acc[r] : -60.0f; mx = fmaxf(mx, l[r]); }
        float s = 0.0f;
        #pragma unroll
        for (int r = 0; r < 7; r++) { l[r] = __expf(l[r] - mx); s += l[r]; }
        const float inv = __fdividef(1.0f, s);
        float* ro = out + 5120;
        #pragma unroll
        for (int r = 0; r < 7; r++) ro[((size_t)b * 7 + r) * 32 + n] = l[r] * inv;
    }

    // ---- instr + value: bwd block only, 4 lanes per sample (tid < 64)
    if (dir == 1 && tid < 64) {
        const int b    = b0 + (tid >> 2);
        const int lane4 = tid & 3;

        float acc[6];
        #pragma unroll
        for (int a = 0; a < 6; a++) acc[a] = 0.0f;

        const float4* af = (const float4*)(g_af + (size_t)b * 60);
        const float4* ab = (const float4*)(g_ab + (size_t)b * 60);
        for (int q = lane4; q < 30; q += 4) {
            const float4 f = (q < 15) ? af[q] : ab[q - 15];
            #pragma unroll
            for (int a = 0; a < 5; a++) {
                const float4 w = *(const float4*)(sm + HW_WA + a * 120 + q * 4);
                acc[a] += w.x*f.x + w.y*f.y + w.z*f.z + w.w*f.w;
            }
            const float4 wc = *(const float4*)(sm + HW_WC + q * 4);
            acc[5] += wc.x*f.x + wc.y*f.y + wc.z*f.z + wc.w*f.w;
        }
        #pragma unroll
        for (int off = 1; off < 4; off <<= 1) {
            #pragma unroll
            for (int a = 0; a < 6; a++)
                acc[a] += __shfl_xor_sync(0xffffffffu, acc[a], off);
        }
        if (lane4 == 0) {
            float l[5], mx = -1e30f;
            #pragma unroll
            for (int a = 0; a < 5; a++) { l[a] = acc[a] + sm[HW_BA + a]; mx = fmaxf(mx, l[a]); }
            float s = 0.0f;
            #pragma unroll
            for (int a = 0; a < 5; a++) { l[a] = __expf(l[a] - mx); s += l[a]; }
            const float inv = __fdividef(1.0f, s);
            #pragma unroll
            for (int a = 0; a < 5; a++) out[b * 5 + a] = l[a] * inv;
            out[5120 + Bsz * 7 * Nn + b] = acc[5] + sm[HW_BC];   // value @ 234496
        }
    }
}

// ============================================================
extern "C" void kernel_launch(void* const* d_in, const int* in_sizes, int n_in,
                              void* d_out, int out_size)
{
    const float* has   = (const float*)d_in[0];
    const float* z     = (const float*)d_in[1];
    const float* dz    = (const float*)d_in[2];
    const unsigned char* adj = (const unsigned char*)d_in[3];
    const float* Wih_f = (const float*)d_in[4];
    const float* Whh_f = (const float*)d_in[5];
    const float* bih_f = (const float*)d_in[6];
    const float* bhh_f = (const float*)d_in[7];
    const float* Wih_b = (const float*)d_in[8];
    const float* Whh_b = (const float*)d_in[9];
    const float* bih_b = (const float*)d_in[10];
    const float* bhh_b = (const float*)d_in[11];
    const float* Wf    = (const float*)d_in[12];
    const float* bf    = (const float*)d_in[13];
    const float* Wb    = (const float*)d_in[14];
    const float* bb    = (const float*)d_in[15];
    const float* Wa    = (const float*)d_in[16];
    const float* ba    = (const float*)d_in[17];
    const float* Wc    = (const float*)d_in[18];
    const float* bc    = (const float*)d_in[19];
    const float* Wu    = (const float*)d_in[20];
    const float* bu    = (const float*)d_in[21];
    float* out = (float*)d_out;

    const size_t smem = SMEM_FLOATS * sizeof(float);   // ~139 KB -> 1 block/SM
    cudaFuncSetAttribute(k_scan, cudaFuncAttributeMaxDynamicSharedMemorySize, (int)smem);

    k_scan<<<128, TPB, smem>>>(adj, has, z, dz,
                               Wih_f, Whh_f, bih_f, bhh_f,
                               Wih_b, Whh_b, bih_b, bhh_b,
                               Wf, bf, Wb, bb,
                               Wu, bu, Wa, ba, Wc, bc, out);
}